// round 1
// baseline (speedup 1.0000x reference)
#include <cuda_runtime.h>
#include <math.h>

#define BATCH 1024
#define NAG   8
#define NDUM  16
#define PLAN  128
#define HID   256
#define TP    256      /* 2*PLAN  */
#define G3    768      /* 3*HID   */
#define TB    16384    /* NDUM*BATCH */
#define AD    16       /* agents*dirs */

/* ---------------- static device scratch (alloc-free rule) ---------------- */
__device__ float g_comm[BATCH*NAG*PLAN];
__device__ int   g_empty[BATCH];
__device__ int   g_mask[TB];
__device__ int   g_seq[BATCH];
__device__ int   g_srclist[TB];
__device__ int   g_packsrc[TB];
__device__ int   g_scatrank[TB];
__device__ float g_cseq[(size_t)NAG*TB*TP];
__device__ float g_gi[(size_t)NAG*TB*1536];
__device__ float g_gh[(size_t)AD*BATCH*G3];
__device__ float g_h[(size_t)AD*BATCH*HID];
__device__ float g_out[(size_t)AD*TB*HID];
__device__ float g_scores[(size_t)NAG*TB*512];
__device__ float g_h1[(size_t)NAG*TB*HID];
__device__ float g_Wcat[(size_t)NAG*1536*TP];
__device__ float g_Whcat[(size_t)AD*G3*HID];

/* ---------------- small setup kernels ---------------- */

__global__ void k_empty(const float* __restrict__ comm_plans) {
    int b = blockIdx.x;
    const float* p = comm_plans + (size_t)b*NAG*PLAN;
    int tid = threadIdx.x;
    int nz = 0;
    for (int i = tid; i < NAG*PLAN; i += 256) nz |= (p[i] != 0.0f);
    __shared__ int s[256];
    s[tid] = nz; __syncthreads();
    for (int st = 128; st > 0; st >>= 1) { if (tid < st) s[tid] |= s[tid+st]; __syncthreads(); }
    if (tid == 0) g_empty[b] = (s[0] == 0);
}

__global__ void k_comm(const float* __restrict__ plans, const float* __restrict__ comm_plans) {
    int bn = blockIdx.x;            /* b*8+n */
    int b = bn >> 3, n = bn & 7;
    int p = threadIdx.x;            /* 128 threads */
    float v = g_empty[b] ? plans[(size_t)bn*PLAN + p] : comm_plans[(size_t)bn*PLAN + p];
    g_comm[(size_t)bn*PLAN + p] = v;
    unsigned ball = __ballot_sync(0xffffffffu, v != 0.0f);
    __shared__ int s[4];
    if ((p & 31) == 0) s[p >> 5] = (ball != 0);
    __syncthreads();
    if (p == 0) g_mask[n*BATCH + b] = (s[0]|s[1]|s[2]|s[3]) ? 1 : 0;
}

__global__ void k_seq() {
    int b = blockIdx.x*blockDim.x + threadIdx.x;
    if (b >= BATCH) return;
    int s = 8;
    for (int n = 0; n < NAG; n++) s += g_mask[n*BATCH + b];
    g_seq[b] = s;
    for (int t = NAG; t < NDUM; t++) g_mask[t*BATCH + b] = 1;
}

/* flat row-major rank matching for pack / scatter (torch masked semantics) */
__global__ void k_scan() {
    __shared__ int pm_off[512], mk_off[512];
    int tid = threadIdx.x;
    int base = tid * 32;
    int cm = 0, cp = 0;
    for (int j = base; j < base+32; j++) {
        cm += g_mask[j];
        int t = j >> 10, b = j & 1023;
        cp += (t < g_seq[b]);
    }
    mk_off[tid] = cm; pm_off[tid] = cp;
    __syncthreads();
    if (tid == 0) {
        int am = 0, ap = 0;
        for (int i = 0; i < 512; i++) {
            int tm = mk_off[i], tpv = pm_off[i];
            mk_off[i] = am; pm_off[i] = ap;
            am += tm; ap += tpv;
        }
    }
    __syncthreads();
    int rm = mk_off[tid];
    for (int j = base; j < base+32; j++) {
        if (g_mask[j]) { g_srclist[rm] = j; g_scatrank[j] = rm; rm++; }
        else           { g_scatrank[j] = -1; }
    }
    __syncthreads();
    int rp = pm_off[tid];
    for (int j = base; j < base+32; j++) {
        int t = j >> 10, b = j & 1023;
        if (t < g_seq[b]) { g_packsrc[j] = g_srclist[rp]; rp++; }
        else              { g_packsrc[j] = -1; }
    }
}

__global__ void k_wcat(const float* __restrict__ Wi_f, const float* __restrict__ Wi_b) {
    size_t idx = (size_t)blockIdx.x*256 + threadIdx.x;
    if (idx >= (size_t)NAG*1536*TP) return;
    int k = (int)(idx & 255);
    size_t r = idx >> 8;
    int g = (int)(r % 1536);
    int a = (int)(r / 1536);
    float v = (g < G3) ? Wi_f[((size_t)a*G3 + g)*TP + k]
                       : Wi_b[((size_t)a*G3 + (g - G3))*TP + k];
    g_Wcat[idx] = v;
}

__global__ void k_whcat(const float* __restrict__ Wh_f, const float* __restrict__ Wh_b) {
    size_t idx = (size_t)blockIdx.x*256 + threadIdx.x;
    if (idx >= (size_t)AD*G3*HID) return;
    int k = (int)(idx & 255);
    size_t r = idx >> 8;
    int g = (int)(r % G3);
    int z = (int)(r / G3);
    int a = z >> 1, d = z & 1;
    const float* W = d ? Wh_b : Wh_f;
    g_Whcat[idx] = W[((size_t)a*G3 + g)*HID + k];
}

__global__ void k_hinit(const float* __restrict__ hx) {
    size_t idx = (size_t)blockIdx.x*256 + threadIdx.x;
    if (idx >= (size_t)AD*BATCH*HID/4) return;
    ((float4*)g_h)[idx] = ((const float4*)hx)[idx];
}

/* build packed sequence input per agent (gathers via pack_src) */
__global__ void k_cseq(const float* __restrict__ plans, const float* __restrict__ dummy) {
    size_t idx = (size_t)blockIdx.x*256 + threadIdx.x;
    if (idx >= (size_t)NAG*TB*64) return;
    int c4 = (int)(idx & 63);
    size_t r = idx >> 6;
    int j = (int)(r % TB);
    int a = (int)(r / TB);
    float4 v = make_float4(0.f,0.f,0.f,0.f);
    int s = g_packsrc[j];
    if (s >= 0) {
        int t = s >> 10, b = s & 1023;
        if (t < NAG) {
            if (c4 < 32)
                v = ((const float4*)(plans + (size_t)(b*NAG + a)*PLAN))[c4];
            else
                v = ((const float4*)(g_comm + (size_t)(b*NAG + t)*PLAN))[c4 - 32];
        } else {
            v = ((const float4*)(dummy + ((size_t)(a*(NDUM-NAG) + (t - NAG))*BATCH + b)*TP))[c4];
        }
    }
    ((float4*)(g_cseq + ((size_t)a*TB + j)*TP))[c4] = v;
}

/* ---------------- 128x128x8 SGEMM (NT: C = A * Bw^T), batched by z ---------------- */
/* mode 0: gi = cseq @ Wcat^T  (M=16384,N=1536,K=256, z=agent)
   mode 1: gh = h    @ Whcat^T (M=1024, N=768, K=256, z=agentdir)
   mode 2: h1 = relu(scores @ W1^T + b1) (M=16384,N=256,K=512, z=agent) */
__global__ void __launch_bounds__(256) sgemm_nt(int mode, const float* __restrict__ Wext,
                                                const float* __restrict__ biasExt) {
    const float* A; const float* Bw; float* C; const float* bias = 0;
    int Kdim, Ndim, relu = 0;
    int zb = blockIdx.z;
    if (mode == 0) {
        A = g_cseq + (size_t)zb*TB*TP;   Bw = g_Wcat  + (size_t)zb*1536*TP;
        C = g_gi   + (size_t)zb*TB*1536; Kdim = TP;  Ndim = 1536;
    } else if (mode == 1) {
        A = g_h    + (size_t)zb*BATCH*HID; Bw = g_Whcat + (size_t)zb*G3*HID;
        C = g_gh   + (size_t)zb*BATCH*G3;  Kdim = HID; Ndim = G3;
    } else {
        A = g_scores + (size_t)zb*TB*512; Bw = Wext + (size_t)zb*HID*512;
        C = g_h1     + (size_t)zb*TB*HID; bias = biasExt + zb*HID;
        Kdim = 512; Ndim = HID; relu = 1;
    }
    const int m0 = blockIdx.x * 128;
    const int n0 = blockIdx.y * 128;
    __shared__ float As[8][128];
    __shared__ float Bs[8][128];
    const int tid  = threadIdx.x;
    const int aRow = tid >> 1;
    const int aK   = (tid & 1) << 2;
    const int ty   = tid >> 4;
    const int tx   = tid & 15;
    const float* Ag = A  + (size_t)(m0 + aRow)*Kdim + aK;
    const float* Bg = Bw + (size_t)(n0 + aRow)*Kdim + aK;
    float acc[8][8];
    #pragma unroll
    for (int i = 0; i < 8; i++)
        #pragma unroll
        for (int j = 0; j < 8; j++) acc[i][j] = 0.f;
    int ktiles = Kdim >> 3;
    float4 pa = *(const float4*)Ag;
    float4 pb = *(const float4*)Bg;
    for (int kt = 0; kt < ktiles; ++kt) {
        As[aK+0][aRow]=pa.x; As[aK+1][aRow]=pa.y; As[aK+2][aRow]=pa.z; As[aK+3][aRow]=pa.w;
        Bs[aK+0][aRow]=pb.x; Bs[aK+1][aRow]=pb.y; Bs[aK+2][aRow]=pb.z; Bs[aK+3][aRow]=pb.w;
        __syncthreads();
        if (kt + 1 < ktiles) {
            pa = *(const float4*)(Ag + (size_t)(kt+1)*8);
            pb = *(const float4*)(Bg + (size_t)(kt+1)*8);
        }
        #pragma unroll
        for (int k = 0; k < 8; k++) {
            float4 a0 = *(const float4*)&As[k][ty<<3];
            float4 a1 = *(const float4*)&As[k][(ty<<3)+4];
            float4 b0 = *(const float4*)&Bs[k][tx<<3];
            float4 b1 = *(const float4*)&Bs[k][(tx<<3)+4];
            float av[8] = {a0.x,a0.y,a0.z,a0.w,a1.x,a1.y,a1.z,a1.w};
            float bv[8] = {b0.x,b0.y,b0.z,b0.w,b1.x,b1.y,b1.z,b1.w};
            #pragma unroll
            for (int i = 0; i < 8; i++)
                #pragma unroll
                for (int j = 0; j < 8; j++)
                    acc[i][j] = fmaf(av[i], bv[j], acc[i][j]);
        }
        __syncthreads();
    }
    #pragma unroll
    for (int i = 0; i < 8; i++) {
        int m = m0 + (ty<<3) + i;
        float* crow = C + (size_t)m*Ndim + n0 + (tx<<3);
        float v[8];
        #pragma unroll
        for (int j = 0; j < 8; j++) v[j] = acc[i][j];
        if (bias) {
            #pragma unroll
            for (int j = 0; j < 8; j++) v[j] += bias[n0 + (tx<<3) + j];
        }
        if (relu) {
            #pragma unroll
            for (int j = 0; j < 8; j++) v[j] = fmaxf(v[j], 0.f);
        }
        *(float4*)crow     = make_float4(v[0],v[1],v[2],v[3]);
        *(float4*)(crow+4) = make_float4(v[4],v[5],v[6],v[7]);
    }
}

/* ---------------- GRU gate update (fwd+bwd), step t ---------------- */
__global__ void k_gate(int t) {
    size_t idx = (size_t)blockIdx.x*256 + threadIdx.x;    /* AD*BATCH*HID */
    if (idx >= (size_t)AD*BATCH*HID) return;
    int i = (int)(idx & 255);
    int b = (int)((idx >> 8) & 1023);
    int z = (int)(idx >> 18);
    int sl = g_seq[b];
    if (t >= sl) return;                                  /* invalid for both dirs */
    int a = z >> 1, d = z & 1;
    int ot = d ? (sl - 1 - t) : t;                        /* backward walks from the end */
    const float* gi = g_gi + ((size_t)a*TB + (size_t)ot*BATCH + b)*1536 + d*G3;
    const float* gh = g_gh + ((size_t)z*BATCH + b)*G3;
    size_t hidx = ((size_t)z*BATCH + b)*HID + i;
    float h  = g_h[hidx];
    float rr = 1.f/(1.f + expf(-(gi[i]        + gh[i])));
    float zz = 1.f/(1.f + expf(-(gi[HID+i]    + gh[HID+i])));
    float nn = tanhf(gi[2*HID+i] + rr*gh[2*HID+i]);
    float hn = (1.f - zz)*nn + zz*h;
    g_h[hidx] = hn;
    g_out[((size_t)z*TB + (size_t)ot*BATCH + b)*HID + i] = hn;
}

/* ---------------- scatter + LayerNorm ---------------- */
__global__ void k_scatln(const float* __restrict__ gamma, const float* __restrict__ beta) {
    int j = blockIdx.x, a = blockIdx.y;
    int tid = threadIdx.x;                                /* 128 */
    int c = tid * 4;
    float4 v = make_float4(0.f,0.f,0.f,0.f);
    if (g_mask[j]) {
        int r = g_scatrank[j];                            /* flat read position into s */
        int d  = (c >= HID) ? 1 : 0;
        int cc = d ? c - HID : c;
        v = *(const float4*)(g_out + ((size_t)(a*2 + d)*TB + r)*HID + cc);
    }
    __shared__ float red[128];
    red[tid] = v.x + v.y + v.z + v.w;
    __syncthreads();
    for (int st = 64; st > 0; st >>= 1) { if (tid < st) red[tid] += red[tid+st]; __syncthreads(); }
    float mu = red[0] * (1.f/512.f);
    __syncthreads();
    float d0 = v.x-mu, d1 = v.y-mu, d2 = v.z-mu, d3 = v.w-mu;
    red[tid] = d0*d0 + d1*d1 + d2*d2 + d3*d3;
    __syncthreads();
    for (int st = 64; st > 0; st >>= 1) { if (tid < st) red[tid] += red[tid+st]; __syncthreads(); }
    float rstd = rsqrtf(red[0]*(1.f/512.f) + 1e-5f);
    float4 gg = ((const float4*)(gamma + (size_t)a*512))[tid];
    float4 bb = ((const float4*)(beta  + (size_t)a*512))[tid];
    float4 o;
    o.x = d0*rstd*gg.x + bb.x;
    o.y = d1*rstd*gg.y + bb.y;
    o.z = d2*rstd*gg.z + bb.z;
    o.w = d3*rstd*gg.w + bb.w;
    ((float4*)(g_scores + ((size_t)a*TB + j)*512))[tid] = o;
}

/* ---------------- final 2-wide projection -> coord_masks ---------------- */
__global__ void k_out2(const float* __restrict__ W2, const float* __restrict__ b2,
                       float* __restrict__ out) {
    size_t w = ((size_t)blockIdx.x*blockDim.x + threadIdx.x) >> 5;
    int lane = threadIdx.x & 31;
    if (w >= (size_t)NAG*TB) return;
    int j = (int)(w % TB);
    int a = (int)(w / TB);
    const float* h1 = g_h1 + ((size_t)a*TB + j)*HID;
    const float* w0 = W2 + (size_t)a*2*HID;
    const float* w1 = w0 + HID;
    float p0 = 0.f, p1 = 0.f;
    for (int k = lane*4; k < HID; k += 128) {
        float4 hv = *(const float4*)(h1 + k);
        float4 a0 = *(const float4*)(w0 + k);
        float4 a1 = *(const float4*)(w1 + k);
        p0 += hv.x*a0.x + hv.y*a0.y + hv.z*a0.z + hv.w*a0.w;
        p1 += hv.x*a1.x + hv.y*a1.y + hv.z*a1.z + hv.w*a1.w;
    }
    for (int s = 16; s > 0; s >>= 1) {
        p0 += __shfl_xor_sync(0xffffffffu, p0, s);
        p1 += __shfl_xor_sync(0xffffffffu, p1, s);
    }
    if (lane == 0) {
        out[w*2 + 0] = p0 + b2[a*2 + 0];
        out[w*2 + 1] = p1 + b2[a*2 + 1];
    }
}

__global__ void k_hcopy(float* __restrict__ out) {
    size_t idx = (size_t)blockIdx.x*256 + threadIdx.x;
    if (idx >= (size_t)AD*BATCH*HID/4) return;
    ((float4*)out)[idx] = ((const float4*)g_h)[idx];
}

/* ---------------- launcher ---------------- */
extern "C" void kernel_launch(void* const* d_in, const int* in_sizes, int n_in,
                              void* d_out, int out_size) {
    const float* plans      = (const float*)d_in[0];
    const float* comm_plans = (const float*)d_in[1];
    const float* hx         = (const float*)d_in[2];
    const float* dummy      = (const float*)d_in[3];
    const float* Wi_f       = (const float*)d_in[4];
    const float* Wh_f       = (const float*)d_in[5];
    const float* Wi_b       = (const float*)d_in[6];
    const float* Wh_b       = (const float*)d_in[7];
    const float* ln_g       = (const float*)d_in[8];
    const float* ln_b       = (const float*)d_in[9];
    const float* W1         = (const float*)d_in[10];
    const float* b1         = (const float*)d_in[11];
    const float* W2         = (const float*)d_in[12];
    const float* b2         = (const float*)d_in[13];
    float* out = (float*)d_out;

    k_empty<<<BATCH, 256>>>(comm_plans);
    k_comm<<<BATCH*NAG, 128>>>(plans, comm_plans);
    k_seq<<<4, 256>>>();
    k_scan<<<1, 512>>>();
    k_wcat<<<(NAG*1536*TP + 255)/256, 256>>>(Wi_f, Wi_b);
    k_whcat<<<(AD*G3*HID + 255)/256, 256>>>(Wh_f, Wh_b);
    k_hinit<<<(AD*BATCH*HID/4 + 255)/256, 256>>>(hx);
    k_cseq<<<(NAG*TB*64 + 255)/256, 256>>>(plans, dummy);

    /* input projections (both directions, all agents) */
    {
        dim3 g(TB/128, 1536/128, NAG);
        sgemm_nt<<<g, 256>>>(0, (const float*)0, (const float*)0);
    }

    /* 16 recurrent steps: gh GEMM + fused gate update */
    for (int t = 0; t < NDUM; t++) {
        dim3 g(BATCH/128, G3/128, AD);
        sgemm_nt<<<g, 256>>>(1, (const float*)0, (const float*)0);
        k_gate<<<(AD*BATCH*HID + 255)/256, 256>>>(t);
    }

    /* final hidden states -> d_out (coord_rnn_hxs region) */
    k_hcopy<<<(AD*BATCH*HID/4 + 255)/256, 256>>>(out + (size_t)NAG*NDUM*BATCH*2);

    /* scatter + LayerNorm */
    {
        dim3 g(TB, NAG);
        k_scatln<<<g, 128>>>(ln_g, ln_b);
    }

    /* MLP layer 1 (bias+relu fused) */
    {
        dim3 g(TB/128, HID/128, NAG);
        sgemm_nt<<<g, 256>>>(2, W1, b1);
    }

    /* final projection -> coord_masks region of d_out */
    k_out2<<<(NAG*TB*32 + 255)/256, 256>>>(W2, b2, out);
}

// round 2
// speedup vs baseline: 2.0879x; 2.0879x over previous
#include <cuda_runtime.h>
#include <math.h>

#define BATCH 1024
#define NAG   8
#define NDUM  16
#define PLAN  128
#define HID   256
#define TP    256      /* 2*PLAN  */
#define G3    768      /* 3*HID   */
#define TB    16384    /* NDUM*BATCH */
#define AD    16       /* agents*dirs */

/* ---------------- static device scratch (alloc-free rule) ---------------- */
__device__ float g_comm[BATCH*NAG*PLAN];
__device__ int   g_empty[BATCH];
__device__ int   g_mask[TB];
__device__ int   g_seq[BATCH];
__device__ int   g_srclist[TB];
__device__ int   g_packsrc[TB];
__device__ int   g_scatrank[TB];
__device__ float g_cseq[(size_t)NAG*TB*TP];
__device__ float g_gi[(size_t)NAG*TB*1536];
__device__ float g_gh[(size_t)AD*BATCH*G3];
__device__ float g_h[(size_t)AD*BATCH*HID];
__device__ float g_out[(size_t)AD*TB*HID];
__device__ float g_scores[(size_t)NAG*TB*512];
__device__ float g_h1[(size_t)NAG*TB*HID];
__device__ float g_Wcat[(size_t)NAG*1536*TP];
__device__ float g_Whcat[(size_t)AD*G3*HID];

/* ---------------- small setup kernels ---------------- */

__global__ void k_empty(const float* __restrict__ comm_plans) {
    int b = blockIdx.x;
    const float* p = comm_plans + (size_t)b*NAG*PLAN;
    int tid = threadIdx.x;
    int nz = 0;
    for (int i = tid; i < NAG*PLAN; i += 256) nz |= (p[i] != 0.0f);
    __shared__ int s[256];
    s[tid] = nz; __syncthreads();
    for (int st = 128; st > 0; st >>= 1) { if (tid < st) s[tid] |= s[tid+st]; __syncthreads(); }
    if (tid == 0) g_empty[b] = (s[0] == 0);
}

__global__ void k_comm(const float* __restrict__ plans, const float* __restrict__ comm_plans) {
    int bn = blockIdx.x;            /* b*8+n */
    int b = bn >> 3, n = bn & 7;
    int p = threadIdx.x;            /* 128 threads */
    float v = g_empty[b] ? plans[(size_t)bn*PLAN + p] : comm_plans[(size_t)bn*PLAN + p];
    g_comm[(size_t)bn*PLAN + p] = v;
    unsigned ball = __ballot_sync(0xffffffffu, v != 0.0f);
    __shared__ int s[4];
    if ((p & 31) == 0) s[p >> 5] = (ball != 0);
    __syncthreads();
    if (p == 0) g_mask[n*BATCH + b] = (s[0]|s[1]|s[2]|s[3]) ? 1 : 0;
}

__global__ void k_seq() {
    int b = blockIdx.x*blockDim.x + threadIdx.x;
    if (b >= BATCH) return;
    int s = 8;
    for (int n = 0; n < NAG; n++) s += g_mask[n*BATCH + b];
    g_seq[b] = s;
    for (int t = NAG; t < NDUM; t++) g_mask[t*BATCH + b] = 1;
}

/* flat row-major rank matching for pack / scatter (torch masked semantics) */
__global__ void k_scan() {
    __shared__ int wsm[16], wsp[16];
    int tid = threadIdx.x;                 /* 512 */
    int lane = tid & 31, w = tid >> 5;
    int base = tid * 32;
    int cm = 0, cp = 0;
    for (int j = base; j < base+32; j++) {
        cm += g_mask[j];
        int t = j >> 10, b = j & 1023;
        cp += (t < g_seq[b]);
    }
    int im = cm, ip = cp;
    #pragma unroll
    for (int o = 1; o < 32; o <<= 1) {
        int v = __shfl_up_sync(0xffffffffu, im, o); if (lane >= o) im += v;
        v     = __shfl_up_sync(0xffffffffu, ip, o); if (lane >= o) ip += v;
    }
    if (lane == 31) { wsm[w] = im; wsp[w] = ip; }
    __syncthreads();
    if (tid == 0) {
        int am = 0, ap = 0;
        for (int i = 0; i < 16; i++) {
            int t = wsm[i]; wsm[i] = am; am += t;
            t = wsp[i];     wsp[i] = ap; ap += t;
        }
    }
    __syncthreads();
    int rm = wsm[w] + im - cm;
    for (int j = base; j < base+32; j++) {
        if (g_mask[j]) { g_srclist[rm] = j; g_scatrank[j] = rm; rm++; }
        else           { g_scatrank[j] = -1; }
    }
    __syncthreads();
    int rp = wsp[w] + ip - cp;
    for (int j = base; j < base+32; j++) {
        int t = j >> 10, b = j & 1023;
        if (t < g_seq[b]) { g_packsrc[j] = g_srclist[rp]; rp++; }
        else              { g_packsrc[j] = -1; }
    }
}

__global__ void k_wcat(const float* __restrict__ Wi_f, const float* __restrict__ Wi_b) {
    size_t idx = (size_t)blockIdx.x*256 + threadIdx.x;
    if (idx >= (size_t)NAG*1536*TP) return;
    int k = (int)(idx & 255);
    size_t r = idx >> 8;
    int g = (int)(r % 1536);
    int a = (int)(r / 1536);
    float v = (g < G3) ? Wi_f[((size_t)a*G3 + g)*TP + k]
                       : Wi_b[((size_t)a*G3 + (g - G3))*TP + k];
    g_Wcat[idx] = v;
}

__global__ void k_whcat(const float* __restrict__ Wh_f, const float* __restrict__ Wh_b) {
    size_t idx = (size_t)blockIdx.x*256 + threadIdx.x;
    if (idx >= (size_t)AD*G3*HID) return;
    int k = (int)(idx & 255);
    size_t r = idx >> 8;
    int g = (int)(r % G3);
    int z = (int)(r / G3);
    int a = z >> 1, d = z & 1;
    const float* W = d ? Wh_b : Wh_f;
    g_Whcat[idx] = W[((size_t)a*G3 + g)*HID + k];
}

__global__ void k_hinit(const float* __restrict__ hx) {
    size_t idx = (size_t)blockIdx.x*256 + threadIdx.x;
    if (idx >= (size_t)AD*BATCH*HID/4) return;
    ((float4*)g_h)[idx] = ((const float4*)hx)[idx];
}

/* build packed sequence input per agent (gathers via pack_src) */
__global__ void k_cseq(const float* __restrict__ plans, const float* __restrict__ dummy) {
    size_t idx = (size_t)blockIdx.x*256 + threadIdx.x;
    if (idx >= (size_t)NAG*TB*64) return;
    int c4 = (int)(idx & 63);
    size_t r = idx >> 6;
    int j = (int)(r % TB);
    int a = (int)(r / TB);
    float4 v = make_float4(0.f,0.f,0.f,0.f);
    int s = g_packsrc[j];
    if (s >= 0) {
        int t = s >> 10, b = s & 1023;
        if (t < NAG) {
            if (c4 < 32)
                v = ((const float4*)(plans + (size_t)(b*NAG + a)*PLAN))[c4];
            else
                v = ((const float4*)(g_comm + (size_t)(b*NAG + t)*PLAN))[c4 - 32];
        } else {
            v = ((const float4*)(dummy + ((size_t)(a*(NDUM-NAG) + (t - NAG))*BATCH + b)*TP))[c4];
        }
    }
    ((float4*)(g_cseq + ((size_t)a*TB + j)*TP))[c4] = v;
}

/* ---------------- tf32 tensor-core GEMM (NT: C = A * Bw^T), batched by z ----------------
   mode 0: gi = cseq @ Wcat^T  (M=16384,N=1536,K=256, z=agent)
   mode 1: gh = h    @ Whcat^T (M=1024, N=768, K=256, z=agentdir)
   mode 2: h1 = relu(scores @ W1^T + b1) (M=16384,N=256,K=512, z=agent)
   BM=BN=128, BK=16, 8 warps (2x4), warp tile 64x32, mma.m16n8k8.tf32. */

__device__ __forceinline__ unsigned f2t(float x) {
    unsigned u; asm("cvt.rna.tf32.f32 %0, %1;" : "=r"(u) : "f"(x)); return u;
}

__global__ void __launch_bounds__(256, 2) gemm_tf32(int mode, const float* __restrict__ Wext,
                                                    const float* __restrict__ biasExt) {
    const float* A; const float* Bw; float* C; const float* bias = 0;
    int K, Nd, relu = 0;
    int zb = blockIdx.z;
    if (mode == 0) {
        A = g_cseq + (size_t)zb*TB*TP;   Bw = g_Wcat  + (size_t)zb*1536*TP;
        C = g_gi   + (size_t)zb*TB*1536; K = TP;  Nd = 1536;
    } else if (mode == 1) {
        A = g_h    + (size_t)zb*BATCH*HID; Bw = g_Whcat + (size_t)zb*G3*HID;
        C = g_gh   + (size_t)zb*BATCH*G3;  K = HID; Nd = G3;
    } else {
        A = g_scores + (size_t)zb*TB*512; Bw = Wext + (size_t)zb*HID*512;
        C = g_h1     + (size_t)zb*TB*HID; bias = biasExt + zb*HID;
        K = 512; Nd = HID; relu = 1;
    }
    const int m0 = blockIdx.x * 128;
    const int n0 = blockIdx.y * 128;

    __shared__ unsigned As[2][16][136];   /* [buf][k][m], stride 136 = 8 mod 32 */
    __shared__ unsigned Bs[2][16][136];   /* [buf][k][n] */

    const int tid  = threadIdx.x;
    const int lane = tid & 31;
    const int warp = tid >> 5;
    const int wm   = (warp & 1) << 6;     /* 0 or 64  */
    const int wn   = (warp >> 1) << 5;    /* 0,32,64,96 */
    const int lm   = tid >> 1;            /* 0..127 */
    const int lk   = (tid & 1) << 3;      /* 0 or 8 */

    const float* Ag = A  + (size_t)(m0 + lm)*K + lk;
    const float* Bg = Bw + (size_t)(n0 + lm)*K + lk;

    float acc[4][4][4];
    #pragma unroll
    for (int i = 0; i < 4; i++)
        #pragma unroll
        for (int j = 0; j < 4; j++)
            #pragma unroll
            for (int q = 0; q < 4; q++) acc[i][j][q] = 0.f;

    const int ktiles = K >> 4;
    float4 ra0 = *(const float4*)Ag;
    float4 ra1 = *(const float4*)(Ag + 4);
    float4 rb0 = *(const float4*)Bg;
    float4 rb1 = *(const float4*)(Bg + 4);

#define STORE_TILE(buf) do {                                               \
    As[buf][lk+0][lm]=f2t(ra0.x); As[buf][lk+1][lm]=f2t(ra0.y);            \
    As[buf][lk+2][lm]=f2t(ra0.z); As[buf][lk+3][lm]=f2t(ra0.w);            \
    As[buf][lk+4][lm]=f2t(ra1.x); As[buf][lk+5][lm]=f2t(ra1.y);            \
    As[buf][lk+6][lm]=f2t(ra1.z); As[buf][lk+7][lm]=f2t(ra1.w);            \
    Bs[buf][lk+0][lm]=f2t(rb0.x); Bs[buf][lk+1][lm]=f2t(rb0.y);            \
    Bs[buf][lk+2][lm]=f2t(rb0.z); Bs[buf][lk+3][lm]=f2t(rb0.w);            \
    Bs[buf][lk+4][lm]=f2t(rb1.x); Bs[buf][lk+5][lm]=f2t(rb1.y);            \
    Bs[buf][lk+6][lm]=f2t(rb1.z); Bs[buf][lk+7][lm]=f2t(rb1.w); } while(0)

    STORE_TILE(0);
    __syncthreads();

    for (int kt = 0; kt < ktiles; ++kt) {
        const int cur = kt & 1;
        if (kt + 1 < ktiles) {
            const float* Ap = Ag + ((size_t)(kt+1) << 4);
            const float* Bp = Bg + ((size_t)(kt+1) << 4);
            ra0 = *(const float4*)Ap; ra1 = *(const float4*)(Ap + 4);
            rb0 = *(const float4*)Bp; rb1 = *(const float4*)(Bp + 4);
        }
        #pragma unroll
        for (int k8 = 0; k8 < 16; k8 += 8) {
            const int kr = k8 + (lane & 3);
            const int rr = wm + (lane >> 2);
            const int nn = wn + (lane >> 2);
            unsigned af[4][4], bf[4][2];
            #pragma unroll
            for (int i = 0; i < 4; i++) {
                af[i][0] = As[cur][kr  ][rr + i*16];
                af[i][1] = As[cur][kr  ][rr + i*16 + 8];
                af[i][2] = As[cur][kr+4][rr + i*16];
                af[i][3] = As[cur][kr+4][rr + i*16 + 8];
            }
            #pragma unroll
            for (int j = 0; j < 4; j++) {
                bf[j][0] = Bs[cur][kr  ][nn + j*8];
                bf[j][1] = Bs[cur][kr+4][nn + j*8];
            }
            #pragma unroll
            for (int i = 0; i < 4; i++)
                #pragma unroll
                for (int j = 0; j < 4; j++) {
                    asm volatile(
                        "mma.sync.aligned.m16n8k8.row.col.f32.tf32.tf32.f32 "
                        "{%0,%1,%2,%3},{%4,%5,%6,%7},{%8,%9},{%0,%1,%2,%3};"
                        : "+f"(acc[i][j][0]), "+f"(acc[i][j][1]),
                          "+f"(acc[i][j][2]), "+f"(acc[i][j][3])
                        : "r"(af[i][0]), "r"(af[i][1]), "r"(af[i][2]), "r"(af[i][3]),
                          "r"(bf[j][0]), "r"(bf[j][1]));
                }
        }
        if (kt + 1 < ktiles) STORE_TILE((kt+1) & 1);
        __syncthreads();
    }

    const int cb = (lane & 3) << 1;
    #pragma unroll
    for (int i = 0; i < 4; i++) {
        #pragma unroll
        for (int j = 0; j < 4; j++) {
            int r0 = m0 + wm + i*16 + (lane >> 2);
            int c  = n0 + wn + j*8 + cb;
            float v0 = acc[i][j][0], v1 = acc[i][j][1];
            float v2 = acc[i][j][2], v3 = acc[i][j][3];
            if (bias) {
                float b0 = bias[c], b1 = bias[c+1];
                v0 += b0; v1 += b1; v2 += b0; v3 += b1;
            }
            if (relu) {
                v0 = fmaxf(v0, 0.f); v1 = fmaxf(v1, 0.f);
                v2 = fmaxf(v2, 0.f); v3 = fmaxf(v3, 0.f);
            }
            *(float2*)(C + (size_t)r0*Nd + c)       = make_float2(v0, v1);
            *(float2*)(C + (size_t)(r0+8)*Nd + c)   = make_float2(v2, v3);
        }
    }
}

/* ---------------- GRU gate update (fwd+bwd), step t ---------------- */
__global__ void k_gate(int t) {
    size_t idx = (size_t)blockIdx.x*256 + threadIdx.x;    /* AD*BATCH*HID */
    if (idx >= (size_t)AD*BATCH*HID) return;
    int i = (int)(idx & 255);
    int b = (int)((idx >> 8) & 1023);
    int z = (int)(idx >> 18);
    int sl = g_seq[b];
    if (t >= sl) return;                                  /* invalid for both dirs */
    int a = z >> 1, d = z & 1;
    int ot = d ? (sl - 1 - t) : t;                        /* backward walks from the end */
    const float* gi = g_gi + ((size_t)a*TB + (size_t)ot*BATCH + b)*1536 + d*G3;
    const float* gh = g_gh + ((size_t)z*BATCH + b)*G3;
    size_t hidx = ((size_t)z*BATCH + b)*HID + i;
    float h  = g_h[hidx];
    float rr = 1.f/(1.f + expf(-(gi[i]        + gh[i])));
    float zz = 1.f/(1.f + expf(-(gi[HID+i]    + gh[HID+i])));
    float nn = tanhf(gi[2*HID+i] + rr*gh[2*HID+i]);
    float hn = (1.f - zz)*nn + zz*h;
    g_h[hidx] = hn;
    g_out[((size_t)z*TB + (size_t)ot*BATCH + b)*HID + i] = hn;
}

/* ---------------- scatter + LayerNorm ---------------- */
__global__ void k_scatln(const float* __restrict__ gamma, const float* __restrict__ beta) {
    int j = blockIdx.x, a = blockIdx.y;
    int tid = threadIdx.x;                                /* 128 */
    int c = tid * 4;
    float4 v = make_float4(0.f,0.f,0.f,0.f);
    if (g_mask[j]) {
        int r = g_scatrank[j];                            /* flat read position into s */
        int d  = (c >= HID) ? 1 : 0;
        int cc = d ? c - HID : c;
        v = *(const float4*)(g_out + ((size_t)(a*2 + d)*TB + r)*HID + cc);
    }
    __shared__ float red[128];
    red[tid] = v.x + v.y + v.z + v.w;
    __syncthreads();
    for (int st = 64; st > 0; st >>= 1) { if (tid < st) red[tid] += red[tid+st]; __syncthreads(); }
    float mu = red[0] * (1.f/512.f);
    __syncthreads();
    float d0 = v.x-mu, d1 = v.y-mu, d2 = v.z-mu, d3 = v.w-mu;
    red[tid] = d0*d0 + d1*d1 + d2*d2 + d3*d3;
    __syncthreads();
    for (int st = 64; st > 0; st >>= 1) { if (tid < st) red[tid] += red[tid+st]; __syncthreads(); }
    float rstd = rsqrtf(red[0]*(1.f/512.f) + 1e-5f);
    float4 gg = ((const float4*)(gamma + (size_t)a*512))[tid];
    float4 bb = ((const float4*)(beta  + (size_t)a*512))[tid];
    float4 o;
    o.x = d0*rstd*gg.x + bb.x;
    o.y = d1*rstd*gg.y + bb.y;
    o.z = d2*rstd*gg.z + bb.z;
    o.w = d3*rstd*gg.w + bb.w;
    ((float4*)(g_scores + ((size_t)a*TB + j)*512))[tid] = o;
}

/* ---------------- final 2-wide projection -> coord_masks ---------------- */
__global__ void k_out2(const float* __restrict__ W2, const float* __restrict__ b2,
                       float* __restrict__ out) {
    size_t w = ((size_t)blockIdx.x*blockDim.x + threadIdx.x) >> 5;
    int lane = threadIdx.x & 31;
    if (w >= (size_t)NAG*TB) return;
    int j = (int)(w % TB);
    int a = (int)(w / TB);
    const float* h1 = g_h1 + ((size_t)a*TB + j)*HID;
    const float* w0 = W2 + (size_t)a*2*HID;
    const float* w1 = w0 + HID;
    float p0 = 0.f, p1 = 0.f;
    for (int k = lane*4; k < HID; k += 128) {
        float4 hv = *(const float4*)(h1 + k);
        float4 a0 = *(const float4*)(w0 + k);
        float4 a1 = *(const float4*)(w1 + k);
        p0 += hv.x*a0.x + hv.y*a0.y + hv.z*a0.z + hv.w*a0.w;
        p1 += hv.x*a1.x + hv.y*a1.y + hv.z*a1.z + hv.w*a1.w;
    }
    for (int s = 16; s > 0; s >>= 1) {
        p0 += __shfl_xor_sync(0xffffffffu, p0, s);
        p1 += __shfl_xor_sync(0xffffffffu, p1, s);
    }
    if (lane == 0) {
        out[w*2 + 0] = p0 + b2[a*2 + 0];
        out[w*2 + 1] = p1 + b2[a*2 + 1];
    }
}

__global__ void k_hcopy(float* __restrict__ out) {
    size_t idx = (size_t)blockIdx.x*256 + threadIdx.x;
    if (idx >= (size_t)AD*BATCH*HID/4) return;
    ((float4*)out)[idx] = ((const float4*)g_h)[idx];
}

/* ---------------- launcher ---------------- */
extern "C" void kernel_launch(void* const* d_in, const int* in_sizes, int n_in,
                              void* d_out, int out_size) {
    const float* plans      = (const float*)d_in[0];
    const float* comm_plans = (const float*)d_in[1];
    const float* hx         = (const float*)d_in[2];
    const float* dummy      = (const float*)d_in[3];
    const float* Wi_f       = (const float*)d_in[4];
    const float* Wh_f       = (const float*)d_in[5];
    const float* Wi_b       = (const float*)d_in[6];
    const float* Wh_b       = (const float*)d_in[7];
    const float* ln_g       = (const float*)d_in[8];
    const float* ln_b       = (const float*)d_in[9];
    const float* W1         = (const float*)d_in[10];
    const float* b1         = (const float*)d_in[11];
    const float* W2         = (const float*)d_in[12];
    const float* b2         = (const float*)d_in[13];
    float* out = (float*)d_out;

    k_empty<<<BATCH, 256>>>(comm_plans);
    k_comm<<<BATCH*NAG, 128>>>(plans, comm_plans);
    k_seq<<<4, 256>>>();
    k_scan<<<1, 512>>>();
    k_wcat<<<(NAG*1536*TP + 255)/256, 256>>>(Wi_f, Wi_b);
    k_whcat<<<(AD*G3*HID + 255)/256, 256>>>(Wh_f, Wh_b);
    k_hinit<<<(AD*BATCH*HID/4 + 255)/256, 256>>>(hx);
    k_cseq<<<(NAG*TB*64 + 255)/256, 256>>>(plans, dummy);

    /* input projections (both directions, all agents) */
    {
        dim3 g(TB/128, 1536/128, NAG);
        gemm_tf32<<<g, 256>>>(0, (const float*)0, (const float*)0);
    }

    /* 16 recurrent steps: gh GEMM + fused gate update */
    for (int t = 0; t < NDUM; t++) {
        dim3 g(BATCH/128, G3/128, AD);
        gemm_tf32<<<g, 256>>>(1, (const float*)0, (const float*)0);
        k_gate<<<(AD*BATCH*HID + 255)/256, 256>>>(t);
    }

    /* final hidden states -> d_out (coord_rnn_hxs region) */
    k_hcopy<<<(AD*BATCH*HID/4 + 255)/256, 256>>>(out + (size_t)NAG*NDUM*BATCH*2);

    /* scatter + LayerNorm */
    {
        dim3 g(TB, NAG);
        k_scatln<<<g, 128>>>(ln_g, ln_b);
    }

    /* MLP layer 1 (bias+relu fused) */
    {
        dim3 g(TB/128, HID/128, NAG);
        gemm_tf32<<<g, 256>>>(2, W1, b1);
    }

    /* final projection -> coord_masks region of d_out */
    k_out2<<<(NAG*TB*32 + 255)/256, 256>>>(W2, b2, out);
}